// round 2
// baseline (speedup 1.0000x reference)
#include <cuda_runtime.h>
#include <cub/cub.cuh>
#include <math.h>
#include <float.h>

#define BB 8
#define CC 64
#define NN 65536
#define HEADS 8
#define C3 192
#define TOT (BB*CC*NN)

// ------------------- static scratch -------------------
__device__ __align__(256) float g_x[TOT];                 // sorted x; later aliased as sort values-in (uint)
__device__ __align__(256) float g_qkv[BB*C3*NN];          // qkv; later aliased as sort keys-in (ull)
__device__ __align__(256) float g_dw[BB*C3*NN];           // q,k,v after depthwise
__device__ __align__(256) unsigned long long g_keys1[TOT];
__device__ __align__(256) unsigned int g_vals1[TOT];
__device__ __align__(256) float g_out[TOT];
__device__ unsigned char g_idxh[BB*32*NN];
__device__ unsigned char g_idxw[BB*32*NN];
__device__ float g_nq[BB*CC], g_nk[BB*CC];
__device__ float g_attnraw[BB*HEADS*64];
__device__ float g_attn[BB*HEADS*64];
__device__ float g_chsum[BB*CC], g_chmax[BB*CC], g_ca[BB*CC];
__device__ float g_sp[BB*4*NN];
__device__ float g_sa[BB*NN];
__device__ unsigned char g_cubtmp[768ull*1024ull*1024ull];

// ------------------- helpers -------------------
__device__ __forceinline__ unsigned int fkey(float f) {
    unsigned int u = __float_as_uint(f);
    return (u & 0x80000000u) ? ~u : (u | 0x80000000u);
}
__device__ __forceinline__ float fdec(unsigned int k) {
    return __uint_as_float((k & 0x80000000u) ? (k ^ 0x80000000u) : ~k);
}
__device__ __forceinline__ float sigm(float x) { return 1.0f / (1.0f + expf(-x)); }

// K1: stable sort along h for first 32 channels (8 columns per block, bitonic)
__global__ __launch_bounds__(256) void k_colsort(const float* __restrict__ x) {
    __shared__ unsigned long long sk[256][9];
    int bx = blockIdx.x;
    int wt = bx & 31, c = (bx >> 5) & 31, b = bx >> 10;
    int w0 = wt * 8, t = threadIdx.x;
    const float* src = x + (((b*64 + c)*256 + t)*256 + w0);
#pragma unroll
    for (int q = 0; q < 8; q++)
        sk[t][q] = ((unsigned long long)fkey(src[q]) << 8) | (unsigned)t;
    __syncthreads();
    for (int k = 2; k <= 256; k <<= 1)
        for (int j = k >> 1; j > 0; j >>= 1) {
            for (int m = t; m < 1024; m += 256) {
                int q = m & 7, p = m >> 3;
                int i = ((p & ~(j-1)) << 1) | (p & (j-1));
                int l = i | j;
                bool up = ((i & k) == 0);
                unsigned long long a = sk[i][q], bv = sk[l][q];
                if (up ? (a > bv) : (a < bv)) { sk[i][q] = bv; sk[l][q] = a; }
            }
            __syncthreads();
        }
    float* dst = g_x + (((b*64 + c)*256 + t)*256 + w0);
    unsigned char* di = g_idxh + (((b*32 + c)*256 + t)*256 + w0);
#pragma unroll
    for (int q = 0; q < 8; q++) {
        unsigned long long kk = sk[t][q];
        dst[q] = fdec((unsigned)(kk >> 8));
        di[q] = (unsigned char)(kk & 0xFF);
    }
}

// K2: stable sort along w (after h-sort). 128 threads = 128 comparators.
__global__ __launch_bounds__(128) void k_rowsort() {
    __shared__ unsigned long long sk[256];
    int bx = blockIdx.x;
    int hrow = bx & 255, c = (bx >> 8) & 31, b = bx >> 13;
    int t = threadIdx.x;
    int base = ((b*64 + c)*256 + hrow)*256;
    for (int m = t; m < 256; m += 128)
        sk[m] = ((unsigned long long)fkey(g_x[base + m]) << 8) | (unsigned)m;
    __syncthreads();
    for (int k = 2; k <= 256; k <<= 1)
        for (int j = k >> 1; j > 0; j >>= 1) {
            int i = ((t & ~(j-1)) << 1) | (t & (j-1));
            int l = i | j;
            bool up = ((i & k) == 0);
            unsigned long long a = sk[i], bv = sk[l];
            if (up ? (a > bv) : (a < bv)) { sk[i] = bv; sk[l] = a; }
            __syncthreads();
        }
    for (int m = t; m < 256; m += 128) {
        unsigned long long kk = sk[m];
        g_x[base + m] = fdec((unsigned)(kk >> 8));
        g_idxw[((b*32 + c)*256 + hrow)*256 + m] = (unsigned char)(kk & 0xFF);
    }
}

__global__ __launch_bounds__(256) void k_copyhalf(const float* __restrict__ x) {
    int e = blockIdx.x*256 + threadIdx.x;      // < BB*32*NN
    int b = e >> 21, r = e & ((1<<21)-1);
    int off = (b*64 + 32)*NN + r;
    g_x[off] = x[off];
}

// K3: qkv 1x1 conv GEMM: 64 outputs x 128 pixels per block
__global__ __launch_bounds__(256) void k_qkv(const float* __restrict__ wqkv) {
    __shared__ float xs[64][128];
    __shared__ float ws[64][64];
    int b = blockIdx.z, oc = blockIdx.y;
    int p0 = blockIdx.x * 128, t = threadIdx.x;
    for (int m = t; m < 64*128; m += 256) {
        int c = m >> 7, px = m & 127;
        xs[c][px] = g_x[(b*64 + c)*NN + p0 + px];
    }
    for (int m = t; m < 4096; m += 256) {
        int o = m >> 6, c = m & 63;
        ws[o][c] = wqkv[(oc*64 + o)*64 + c];
    }
    __syncthreads();
    int ob = (t >> 5) * 8, pb = (t & 31) * 4;
    float acc[8][4];
#pragma unroll
    for (int u = 0; u < 8; u++)
#pragma unroll
        for (int v = 0; v < 4; v++) acc[u][v] = 0.0f;
#pragma unroll 8
    for (int c = 0; c < 64; c++) {
        float4 xv = *(const float4*)&xs[c][pb];
        float wv[8];
#pragma unroll
        for (int u = 0; u < 8; u++) wv[u] = ws[ob + u][c];
#pragma unroll
        for (int u = 0; u < 8; u++) {
            acc[u][0] += wv[u]*xv.x; acc[u][1] += wv[u]*xv.y;
            acc[u][2] += wv[u]*xv.z; acc[u][3] += wv[u]*xv.w;
        }
    }
#pragma unroll
    for (int u = 0; u < 8; u++) {
        float4 r; r.x = acc[u][0]; r.y = acc[u][1]; r.z = acc[u][2]; r.w = acc[u][3];
        *(float4*)(g_qkv + ((b*192 + oc*64 + ob + u)*NN + p0 + pb)) = r;
    }
}

// K4: depthwise 3x3 pad 1
__global__ __launch_bounds__(256) void k_dwconv(const float* __restrict__ wdw) {
    int ch = blockIdx.x;                      // b*192 + o
    int o = ch % 192;
    int p = blockIdx.y*256 + threadIdx.x;
    int i = p >> 8, j = p & 255;
    const float* in = g_qkv + ch*NN;
    float wl[9];
#pragma unroll
    for (int q = 0; q < 9; q++) wl[q] = wdw[o*9 + q];
    float acc = 0.0f;
#pragma unroll
    for (int ky = 0; ky < 3; ky++) {
        int ii = i + ky - 1;
        if (ii < 0 || ii > 255) continue;
#pragma unroll
        for (int kx = 0; kx < 3; kx++) {
            int jj = j + kx - 1;
            if (jj < 0 || jj > 255) continue;
            acc += wl[ky*3+kx] * in[ii*256 + jj];
        }
    }
    g_dw[ch*NN + p] = acc;
}

// K5: build composite sort keys from v
__global__ __launch_bounds__(256) void k_mkkeys() {
    int e = blockIdx.x*256 + threadIdx.x;     // < TOT
    int seg = e >> 16, pos = e & 65535;
    int b = seg >> 6, c = seg & 63;
    float v = g_dw[(b*192 + 128 + c)*NN + pos];
    ((unsigned long long*)g_qkv)[e] = ((unsigned long long)seg << 32) | (unsigned long long)fkey(v);
    ((unsigned int*)g_x)[e] = (unsigned int)pos;
}

// K6: per-channel L2 norms of raw q,k (permutation invariant)
__global__ __launch_bounds__(256) void k_norms() {
    int bc = blockIdx.x; int b = bc >> 6, c = bc & 63;
    const float* q = g_dw + (b*192 + c)*NN;
    const float* k = g_dw + (b*192 + 64 + c)*NN;
    float sq = 0.0f, sk2 = 0.0f;
    for (int i = threadIdx.x; i < NN; i += 256) {
        float a = q[i]; sq += a*a;
        float e = k[i]; sk2 += e*e;
    }
    __shared__ float r1[256], r2[256];
    r1[threadIdx.x] = sq; r2[threadIdx.x] = sk2;
    __syncthreads();
    for (int s = 128; s > 0; s >>= 1) {
        if (threadIdx.x < s) { r1[threadIdx.x] += r1[threadIdx.x+s]; r2[threadIdx.x] += r2[threadIdx.x+s]; }
        __syncthreads();
    }
    if (threadIdx.x == 0) { g_nq[bc] = sqrtf(r1[0]); g_nk[bc] = sqrtf(r2[0]); }
}

// K7: raw 8x8 Gram per (b,head) via permuted gathers
__global__ __launch_bounds__(256) void k_attn() {
    int bh = blockIdx.x; int b = bh >> 3, h = bh & 7;
    const float* qp = g_dw + (b*192 + h*8)*NN;
    const float* kp = g_dw + (b*192 + 64 + h*8)*NN;
    const unsigned int* vp = g_vals1 + (b*64 + h*8)*NN;
    float acc[64];
#pragma unroll
    for (int m = 0; m < 64; m++) acc[m] = 0.0f;
    int i0 = blockIdx.y * 4096;
    for (int i = i0 + threadIdx.x; i < i0 + 4096; i += 256) {
        unsigned int id[8]; float qv[8], kv[8];
#pragma unroll
        for (int c = 0; c < 8; c++) id[c] = vp[c*NN + i];
#pragma unroll
        for (int c = 0; c < 8; c++) { qv[c] = qp[c*NN + id[c]]; kv[c] = kp[c*NN + id[c]]; }
#pragma unroll
        for (int c = 0; c < 8; c++)
#pragma unroll
            for (int d = 0; d < 8; d++) acc[c*8+d] += qv[c]*kv[d];
    }
#pragma unroll
    for (int m = 0; m < 64; m++) {
#pragma unroll
        for (int s = 16; s > 0; s >>= 1)
            acc[m] += __shfl_down_sync(0xffffffffu, acc[m], s);
    }
    if ((threadIdx.x & 31) == 0)
#pragma unroll
        for (int m = 0; m < 64; m++)
            atomicAdd(&g_attnraw[bh*64 + m], acc[m]);
}

// K8: normalize + temperature + softmax (8x8 per bh)
__global__ __launch_bounds__(512) void k_softmax(const float* __restrict__ temp) {
    int t = threadIdx.x;                 // 0..511
    int b = t >> 6, h = (t >> 3) & 7, c = t & 7;
    int bh = b*8 + h;
    float nq = fmaxf(g_nq[b*64 + h*8 + c], 1e-12f);
    float tp = temp[h];
    float a[8];
    float mx = -FLT_MAX;
#pragma unroll
    for (int d = 0; d < 8; d++) {
        float nk = fmaxf(g_nk[b*64 + h*8 + d], 1e-12f);
        a[d] = g_attnraw[bh*64 + c*8 + d] / (nq*nk) * tp;
        mx = fmaxf(mx, a[d]);
    }
    float s = 0.0f;
#pragma unroll
    for (int d = 0; d < 8; d++) { a[d] = expf(a[d] - mx); s += a[d]; }
    float inv = 1.0f / s;
#pragma unroll
    for (int d = 0; d < 8; d++) g_attn[bh*64 + c*8 + d] = a[d]*inv;
}

// K9: out = attn @ v_s, scattered back to unsorted positions
__global__ __launch_bounds__(256) void k_av() {
    int bh = blockIdx.y; int b = bh >> 3, h = bh & 7;
    __shared__ float a[64];
    if (threadIdx.x < 64) a[threadIdx.x] = g_attn[bh*64 + threadIdx.x];
    __syncthreads();
    int n = blockIdx.x*256 + threadIdx.x;
    int base = (b*64 + h*8)*NN;
    float v[8]; unsigned int id[8];
#pragma unroll
    for (int d = 0; d < 8; d++) v[d] = fdec((unsigned)g_keys1[base + d*NN + n]);
#pragma unroll
    for (int c = 0; c < 8; c++) id[c] = g_vals1[base + c*NN + n];
#pragma unroll
    for (int c = 0; c < 8; c++) {
        float s = 0.0f;
#pragma unroll
        for (int d = 0; d < 8; d++) s += a[c*8+d]*v[d];
        g_out[base + c*NN + id[c]] = s;
    }
}

// K10: per-channel sum/max over spatial
__global__ __launch_bounds__(256) void k_chstats() {
    int bc = blockIdx.x;
    const float* p = g_out + (size_t)bc*NN;
    float s = 0.0f, m = -FLT_MAX;
    for (int i = threadIdx.x; i < NN; i += 256) { float v = p[i]; s += v; m = fmaxf(m, v); }
    __shared__ float r1[256], r2[256];
    r1[threadIdx.x] = s; r2[threadIdx.x] = m;
    __syncthreads();
    for (int st = 128; st > 0; st >>= 1) {
        if (threadIdx.x < st) { r1[threadIdx.x] += r1[threadIdx.x+st]; r2[threadIdx.x] = fmaxf(r2[threadIdx.x], r2[threadIdx.x+st]); }
        __syncthreads();
    }
    if (threadIdx.x == 0) { g_chsum[bc] = r1[0]; g_chmax[bc] = r2[0]; }
}

// K11: channel attention (tiny MLP)
__global__ __launch_bounds__(64) void k_ca(const float* __restrict__ wfc1, const float* __restrict__ wfc2) {
    int b = blockIdx.x, c = threadIdx.x;
    __shared__ float mv[64], xv[64];
    mv[c] = g_chsum[b*64 + c] * (1.0f/65536.0f);
    xv[c] = g_chmax[b*64 + c];
    __syncthreads();
    float r1[4], r2[4];
#pragma unroll
    for (int j = 0; j < 4; j++) {
        float s1 = 0.0f, s2 = 0.0f;
        for (int cc = 0; cc < 64; cc++) {
            float w = wfc1[j*64 + cc];
            s1 += mv[cc]*w; s2 += xv[cc]*w;
        }
        r1[j] = s1 * sigm(s1);    // silu
        r2[j] = s2 * sigm(s2);
    }
    float t1 = 0.0f, t2 = 0.0f;
#pragma unroll
    for (int j = 0; j < 4; j++) { t1 += r1[j]*wfc2[c*4 + j]; t2 += r2[j]*wfc2[c*4 + j]; }
    g_ca[b*64 + c] = sigm(t1) + sigm(t2);
}

// K12: spatial stats (mean/max/min/sum over channels of out*ca)
__global__ __launch_bounds__(256) void k_sp() {
    int b = blockIdx.y;
    int n = blockIdx.x*256 + threadIdx.x;
    __shared__ float cas[64];
    if (threadIdx.x < 64) cas[threadIdx.x] = g_ca[b*64 + threadIdx.x];
    __syncthreads();
    float s = 0.0f, mx = -FLT_MAX, mn = FLT_MAX;
    for (int c = 0; c < 64; c++) {
        float v = g_out[(b*64 + c)*NN + n] * cas[c];
        s += v; mx = fmaxf(mx, v); mn = fminf(mn, v);
    }
    g_sp[(b*4 + 0)*NN + n] = s * (1.0f/64.0f);
    g_sp[(b*4 + 1)*NN + n] = mx;
    g_sp[(b*4 + 2)*NN + n] = mn;
    g_sp[(b*4 + 3)*NN + n] = s;
}

// K13: 7x7 conv (4->1, pad 3) + silu + scalar 1x1 + sigmoid
__global__ __launch_bounds__(256) void k_sa(const float* __restrict__ wsp1, const float* __restrict__ bsp1,
                                            const float* __restrict__ wsp2, const float* __restrict__ bsp2) {
    __shared__ float tile[4][22][22];
    __shared__ float ws[196];
    int b = blockIdx.z;
    int y0 = blockIdx.y*16, x0 = blockIdx.x*16;
    int tx = threadIdx.x & 15, ty = threadIdx.x >> 4;
    int tid = threadIdx.x;
    if (tid < 196) ws[tid] = wsp1[tid];
    for (int m = tid; m < 4*484; m += 256) {
        int ic = m / 484, rr = m % 484;
        int iy = rr / 22, ix = rr % 22;
        int gy = y0 + iy - 3, gx = x0 + ix - 3;
        tile[ic][iy][ix] = (gy >= 0 && gy < 256 && gx >= 0 && gx < 256)
                           ? g_sp[(b*4 + ic)*NN + gy*256 + gx] : 0.0f;
    }
    __syncthreads();
    float acc = 0.0f;
#pragma unroll
    for (int ic = 0; ic < 4; ic++)
#pragma unroll
        for (int ky = 0; ky < 7; ky++)
#pragma unroll
            for (int kx = 0; kx < 7; kx++)
                acc += ws[ic*49 + ky*7 + kx] * tile[ic][ty+ky][tx+kx];
    float s = acc + bsp1[0];
    float sl = s * sigm(s);
    float t2 = wsp2[0]*sl + bsp2[0];
    g_sa[b*NN + (y0+ty)*256 + x0+tx] = sigm(t2);
}

// K14: projection GEMM fused with ca*sa scaling and inverse permutations (c<32)
__global__ __launch_bounds__(256) void k_proj(const float* __restrict__ wproj, float* __restrict__ out) {
    __shared__ float xs[64][128];
    __shared__ float wp[64][64];
    __shared__ float sas[128];
    __shared__ float cas[64];
    int b = blockIdx.y;
    int p0 = blockIdx.x * 128, t = threadIdx.x;
    if (t < 64) cas[t] = g_ca[b*64 + t];
    if (t < 128) sas[t] = g_sa[b*NN + p0 + t];
    __syncthreads();
    for (int m = t; m < 64*128; m += 256) {
        int c = m >> 7, px = m & 127;
        xs[c][px] = g_out[(b*64 + c)*NN + p0 + px] * cas[c];
    }
    for (int m = t; m < 4096; m += 256) {
        int o = m >> 6, c = m & 63;
        wp[o][c] = wproj[o*64 + c];
    }
    __syncthreads();
    int ob = (t >> 5) * 8, pb = (t & 31) * 4;
    float acc[8][4];
#pragma unroll
    for (int u = 0; u < 8; u++)
#pragma unroll
        for (int v = 0; v < 4; v++) acc[u][v] = 0.0f;
#pragma unroll 8
    for (int c = 0; c < 64; c++) {
        float4 xv = *(const float4*)&xs[c][pb];
        float wv[8];
#pragma unroll
        for (int u = 0; u < 8; u++) wv[u] = wp[ob + u][c];
#pragma unroll
        for (int u = 0; u < 8; u++) {
            acc[u][0] += wv[u]*xv.x; acc[u][1] += wv[u]*xv.y;
            acc[u][2] += wv[u]*xv.z; acc[u][3] += wv[u]*xv.w;
        }
    }
#pragma unroll
    for (int u = 0; u < 8; u++) {
        int o = ob + u;
        if (o >= 32) {
#pragma unroll
            for (int v = 0; v < 4; v++)
                out[(b*64 + o)*NN + p0 + pb + v] = acc[u][v] * sas[pb + v];
        } else {
            int ibase = (b*32 + o) * NN;
#pragma unroll
            for (int v = 0; v < 4; v++) {
                int n = p0 + pb + v;
                int q = n >> 8, p = n & 255;
                int j = (int)g_idxw[ibase + q*256 + p];
                int r = (int)g_idxh[ibase + q*256 + j];
                out[(b*64 + o)*NN + r*256 + j] = acc[u][v] * sas[pb + v];
            }
        }
    }
}

extern "C" void kernel_launch(void* const* d_in, const int* in_sizes, int n_in,
                              void* d_out, int out_size) {
    const float* x     = (const float*)d_in[0];
    const float* temp  = (const float*)d_in[1];
    const float* wqkv  = (const float*)d_in[2];
    const float* wdw   = (const float*)d_in[3];
    const float* wfc1  = (const float*)d_in[4];
    const float* wfc2  = (const float*)d_in[5];
    const float* wsp1  = (const float*)d_in[6];
    const float* bsp1  = (const float*)d_in[7];
    const float* wsp2  = (const float*)d_in[8];
    const float* bsp2  = (const float*)d_in[9];
    const float* wproj = (const float*)d_in[10];
    float* out = (float*)d_out;

    k_colsort<<<8192, 256>>>(x);
    k_rowsort<<<65536, 128>>>();
    k_copyhalf<<<65536, 256>>>(x);
    k_qkv<<<dim3(NN/128, 3, BB), 256>>>(wqkv);
    k_dwconv<<<dim3(BB*C3, NN/256), 256>>>(wdw);
    k_mkkeys<<<TOT/256, 256>>>();

    void *ptmp, *pk0, *pk1, *pv0, *pv1, *pattn;
    cudaGetSymbolAddress(&ptmp, g_cubtmp);
    cudaGetSymbolAddress(&pk0, g_qkv);
    cudaGetSymbolAddress(&pk1, g_keys1);
    cudaGetSymbolAddress(&pv0, g_x);
    cudaGetSymbolAddress(&pv1, g_vals1);
    cudaGetSymbolAddress(&pattn, g_attnraw);
    size_t tb = sizeof(g_cubtmp);
    cub::DeviceRadixSort::SortPairs(ptmp, tb,
        (const unsigned long long*)pk0, (unsigned long long*)pk1,
        (const unsigned int*)pv0, (unsigned int*)pv1,
        TOT, 0, 41);

    k_norms<<<BB*CC, 256>>>();
    cudaMemsetAsync(pattn, 0, sizeof(float)*BB*HEADS*64);
    k_attn<<<dim3(BB*HEADS, 16), 256>>>();
    k_softmax<<<1, 512>>>(temp);
    k_av<<<dim3(NN/256, BB*HEADS), 256>>>();
    k_chstats<<<BB*CC, 256>>>();
    k_ca<<<BB, 64>>>(wfc1, wfc2);
    k_sp<<<dim3(NN/256, BB), 256>>>();
    k_sa<<<dim3(16, 16, BB), 256>>>(wsp1, bsp1, wsp2, bsp2);
    k_proj<<<dim3(NN/128, BB), 256>>>(wproj, out);
}

// round 3
// speedup vs baseline: 1.1762x; 1.1762x over previous
#include <cuda_runtime.h>
#include <math.h>
#include <float.h>

#define BB 8
#define CC 64
#define NN 65536
#define HEADS 8
#define C3 192
#define TOT (BB*CC*NN)
typedef unsigned long long ull;

// ------------------- static scratch -------------------
__device__ __align__(256) float g_x[TOT];                 // sorted x
__device__ __align__(256) float g_qkv[BB*C3*NN];          // qkv; later aliased as sort buffer S0 (ull)
__device__ __align__(256) float g_dw[BB*C3*NN];           // q,k,v after depthwise
__device__ __align__(256) ull g_keys1[TOT];               // sort buffer S1 (final items live here)
__device__ __align__(256) float g_out[TOT];
__device__ unsigned g_cnt[512*16*256];                    // per (seg,block,digit) counts/offsets
__device__ unsigned char g_idxh[BB*32*NN];
__device__ unsigned char g_idxw[BB*32*NN];
__device__ float g_nq[BB*CC], g_nk[BB*CC];
__device__ float g_attnraw[BB*HEADS*64];
__device__ float g_attn[BB*HEADS*64];
__device__ float g_chsum[BB*CC], g_chmax[BB*CC], g_ca[BB*CC];
__device__ float g_sp[BB*4*NN];
__device__ float g_sa[BB*NN];

// ------------------- helpers -------------------
__device__ __forceinline__ unsigned fkey(float f) {
    unsigned u = __float_as_uint(f);
    return (u & 0x80000000u) ? ~u : (u | 0x80000000u);
}
__device__ __forceinline__ float fdec(unsigned k) {
    return __uint_as_float((k & 0x80000000u) ? (k ^ 0x80000000u) : ~k);
}
__device__ __forceinline__ float sigm(float x) { return 1.0f / (1.0f + expf(-x)); }
__device__ __forceinline__ unsigned lmask_lt() {
    unsigned m; asm("mov.u32 %0, %%lanemask_lt;" : "=r"(m)); return m;
}

// K1: stable sort along h for first 32 channels (8 columns per block, bitonic)
__global__ __launch_bounds__(256) void k_colsort(const float* __restrict__ x) {
    __shared__ ull sk[256][9];
    int bx = blockIdx.x;
    int wt = bx & 31, c = (bx >> 5) & 31, b = bx >> 10;
    int w0 = wt * 8, t = threadIdx.x;
    const float* src = x + (((b*64 + c)*256 + t)*256 + w0);
#pragma unroll
    for (int q = 0; q < 8; q++)
        sk[t][q] = ((ull)fkey(src[q]) << 8) | (unsigned)t;
    __syncthreads();
    for (int k = 2; k <= 256; k <<= 1)
        for (int j = k >> 1; j > 0; j >>= 1) {
            for (int m = t; m < 1024; m += 256) {
                int q = m & 7, p = m >> 3;
                int i = ((p & ~(j-1)) << 1) | (p & (j-1));
                int l = i | j;
                bool up = ((i & k) == 0);
                ull a = sk[i][q], bv = sk[l][q];
                if (up ? (a > bv) : (a < bv)) { sk[i][q] = bv; sk[l][q] = a; }
            }
            __syncthreads();
        }
    float* dst = g_x + (((b*64 + c)*256 + t)*256 + w0);
    unsigned char* di = g_idxh + (((b*32 + c)*256 + t)*256 + w0);
#pragma unroll
    for (int q = 0; q < 8; q++) {
        ull kk = sk[t][q];
        dst[q] = fdec((unsigned)(kk >> 8));
        di[q] = (unsigned char)(kk & 0xFF);
    }
}

// K2: stable sort along w (after h-sort)
__global__ __launch_bounds__(128) void k_rowsort() {
    __shared__ ull sk[256];
    int bx = blockIdx.x;
    int hrow = bx & 255, c = (bx >> 8) & 31, b = bx >> 13;
    int t = threadIdx.x;
    int base = ((b*64 + c)*256 + hrow)*256;
    for (int m = t; m < 256; m += 128)
        sk[m] = ((ull)fkey(g_x[base + m]) << 8) | (unsigned)m;
    __syncthreads();
    for (int k = 2; k <= 256; k <<= 1)
        for (int j = k >> 1; j > 0; j >>= 1) {
            int i = ((t & ~(j-1)) << 1) | (t & (j-1));
            int l = i | j;
            bool up = ((i & k) == 0);
            ull a = sk[i], bv = sk[l];
            if (up ? (a > bv) : (a < bv)) { sk[i] = bv; sk[l] = a; }
            __syncthreads();
        }
    for (int m = t; m < 256; m += 128) {
        ull kk = sk[m];
        g_x[base + m] = fdec((unsigned)(kk >> 8));
        g_idxw[((b*32 + c)*256 + hrow)*256 + m] = (unsigned char)(kk & 0xFF);
    }
}

__global__ __launch_bounds__(256) void k_copyhalf(const float* __restrict__ x) {
    int e = blockIdx.x*256 + threadIdx.x;
    int b = e >> 21, r = e & ((1<<21)-1);
    int off = (b*64 + 32)*NN + r;
    g_x[off] = x[off];
}

// K3: qkv 1x1 conv GEMM
__global__ __launch_bounds__(256) void k_qkv(const float* __restrict__ wqkv) {
    __shared__ float xs[64][128];
    __shared__ float ws[64][64];
    int b = blockIdx.z, oc = blockIdx.y;
    int p0 = blockIdx.x * 128, t = threadIdx.x;
    for (int m = t; m < 64*128; m += 256) {
        int c = m >> 7, px = m & 127;
        xs[c][px] = g_x[(b*64 + c)*NN + p0 + px];
    }
    for (int m = t; m < 4096; m += 256) {
        int o = m >> 6, c = m & 63;
        ws[o][c] = wqkv[(oc*64 + o)*64 + c];
    }
    __syncthreads();
    int ob = (t >> 5) * 8, pb = (t & 31) * 4;
    float acc[8][4];
#pragma unroll
    for (int u = 0; u < 8; u++)
#pragma unroll
        for (int v = 0; v < 4; v++) acc[u][v] = 0.0f;
#pragma unroll 8
    for (int c = 0; c < 64; c++) {
        float4 xv = *(const float4*)&xs[c][pb];
        float wv[8];
#pragma unroll
        for (int u = 0; u < 8; u++) wv[u] = ws[ob + u][c];
#pragma unroll
        for (int u = 0; u < 8; u++) {
            acc[u][0] += wv[u]*xv.x; acc[u][1] += wv[u]*xv.y;
            acc[u][2] += wv[u]*xv.z; acc[u][3] += wv[u]*xv.w;
        }
    }
#pragma unroll
    for (int u = 0; u < 8; u++) {
        float4 r; r.x = acc[u][0]; r.y = acc[u][1]; r.z = acc[u][2]; r.w = acc[u][3];
        *(float4*)(g_qkv + ((b*192 + oc*64 + ob + u)*NN + p0 + pb)) = r;
    }
}

// K4: depthwise 3x3 pad 1
__global__ __launch_bounds__(256) void k_dwconv(const float* __restrict__ wdw) {
    int ch = blockIdx.x;
    int o = ch % 192;
    int p = blockIdx.y*256 + threadIdx.x;
    int i = p >> 8, j = p & 255;
    const float* in = g_qkv + ch*NN;
    float wl[9];
#pragma unroll
    for (int q = 0; q < 9; q++) wl[q] = wdw[o*9 + q];
    float acc = 0.0f;
#pragma unroll
    for (int ky = 0; ky < 3; ky++) {
        int ii = i + ky - 1;
        if (ii < 0 || ii > 255) continue;
#pragma unroll
        for (int kx = 0; kx < 3; kx++) {
            int jj = j + kx - 1;
            if (jj < 0 || jj > 255) continue;
            acc += wl[ky*3+kx] * in[ii*256 + jj];
        }
    }
    g_dw[ch*NN + p] = acc;
}

// ==================== custom segmented radix sort ====================
// item = fkey(v)<<16 | pos. Sort bits [24,48) in 3 stable 8-bit LSD passes.
// Segment = (b,c), 65536 items, 16 blocks of 4096 per segment.

// K5: build items into S0 (=g_qkv alias) + histogram for pass 1 (shift 24)
__global__ __launch_bounds__(256) void k_mkkeys(ull* __restrict__ S0) {
    __shared__ unsigned hist[256];
    int t = threadIdx.x;
    hist[t] = 0;
    __syncthreads();
    int base = blockIdx.x * 4096;
    int seg = base >> 16;
    int b = seg >> 6, c = seg & 63;
    const float* vsrc = g_dw + ((size_t)(b*192 + 128 + c))*NN;
#pragma unroll
    for (int r = 0; r < 16; r++) {
        int e = base + r*256 + t;
        int pos = e & 65535;
        unsigned key = fkey(vsrc[pos]);
        S0[e] = ((ull)key << 16) | (unsigned)pos;
        atomicAdd(&hist[(key >> 8) & 255], 1u);
    }
    __syncthreads();
    g_cnt[blockIdx.x*256 + t] = hist[t];
}

// K6: histogram for a pass (digit at `shift`)
__global__ __launch_bounds__(256) void k_count(const ull* __restrict__ src, int shift) {
    __shared__ unsigned hist[256];
    int t = threadIdx.x;
    hist[t] = 0;
    __syncthreads();
    int base = blockIdx.x * 4096;
#pragma unroll
    for (int r = 0; r < 16; r++) {
        ull item = src[base + r*256 + t];
        atomicAdd(&hist[(unsigned)(item >> shift) & 255], 1u);
    }
    __syncthreads();
    g_cnt[blockIdx.x*256 + t] = hist[t];
}

// K7: per-segment scan of counts -> within-segment offsets (in place)
__global__ __launch_bounds__(256) void k_scan() {
    __shared__ unsigned cnt[16][256];
    __shared__ unsigned scn[256];
    int seg = blockIdx.x, t = threadIdx.x;
    for (int blk = 0; blk < 16; blk++)
        cnt[blk][t] = g_cnt[(seg*16 + blk)*256 + t];
    __syncthreads();
    unsigned s = 0;
    for (int blk = 0; blk < 16; blk++) s += cnt[blk][t];
    unsigned mytot = s;
    scn[t] = s;
    __syncthreads();
    for (int off = 1; off < 256; off <<= 1) {
        unsigned v = scn[t];
        unsigned add = (t >= off) ? scn[t - off] : 0;
        __syncthreads();
        scn[t] = v + add;
        __syncthreads();
    }
    unsigned run = scn[t] - mytot;   // exclusive digit base within segment
    for (int blk = 0; blk < 16; blk++) {
        g_cnt[(seg*16 + blk)*256 + t] = run;
        run += cnt[blk][t];
    }
}

// K8: stable scatter pass with local smem staging for coalesced writes
__global__ __launch_bounds__(256) void k_scatter(const ull* __restrict__ src,
                                                 ull* __restrict__ dst, int shift) {
    __shared__ unsigned short runbase[256];
    __shared__ unsigned char wcnt[8][256];
    __shared__ unsigned short rankOf[4096];
    __shared__ unsigned short startLoc[256];
    __shared__ unsigned scn[256];
    __shared__ unsigned offsC[256];
    __shared__ ull stage[4096];

    int t = threadIdx.x;
    int w = t >> 5;
    unsigned ltm = lmask_lt();
    int base = blockIdx.x * 4096;
    int seg = base >> 16;

    runbase[t] = 0;
    offsC[t] = g_cnt[blockIdx.x*256 + t];

    ull it[16];
#pragma unroll
    for (int r = 0; r < 16; r++) it[r] = src[base + r*256 + t];

    for (int r = 0; r < 16; r++) {
        ((ull*)wcnt)[t] = 0ull;
        __syncthreads();
        unsigned d = (unsigned)(it[r] >> shift) & 255u;
        unsigned mask = __match_any_sync(0xffffffffu, d);
        unsigned lr = __popc(mask & ltm);
        if (lr == 0) wcnt[w][d] = (unsigned char)__popc(mask);
        __syncthreads();
        unsigned bdd = runbase[d];
        for (int w2 = 0; w2 < w; w2++) bdd += wcnt[w2][d];
        rankOf[r*256 + t] = (unsigned short)(bdd + lr);
        __syncthreads();
        unsigned s = 0;
#pragma unroll
        for (int w2 = 0; w2 < 8; w2++) s += wcnt[w2][t];
        runbase[t] = (unsigned short)(runbase[t] + s);
        __syncthreads();
    }
    // exclusive scan of runbase -> startLoc
    unsigned mycnt = runbase[t];
    scn[t] = mycnt;
    __syncthreads();
    for (int off = 1; off < 256; off <<= 1) {
        unsigned v = scn[t];
        unsigned add = (t >= off) ? scn[t - off] : 0;
        __syncthreads();
        scn[t] = v + add;
        __syncthreads();
    }
    startLoc[t] = (unsigned short)(scn[t] - mycnt);
    __syncthreads();
    // stage locally in stable-sorted order
#pragma unroll
    for (int r = 0; r < 16; r++) {
        unsigned d = (unsigned)(it[r] >> shift) & 255u;
        stage[startLoc[d] + rankOf[r*256 + t]] = it[r];
    }
    __syncthreads();
    // coalesced-ish global write
    unsigned segbase = (unsigned)seg << 16;
#pragma unroll
    for (int r = 0; r < 16; r++) {
        int j = r*256 + t;
        ull item = stage[j];
        unsigned d = (unsigned)(item >> shift) & 255u;
        dst[segbase + offsC[d] + (unsigned)j - startLoc[d]] = item;
    }
}
// ==================== end sort ====================

// K9: per-channel L2 norms of raw q,k
__global__ __launch_bounds__(256) void k_norms() {
    int bc = blockIdx.x; int b = bc >> 6, c = bc & 63;
    const float* q = g_dw + (b*192 + c)*NN;
    const float* k = g_dw + (b*192 + 64 + c)*NN;
    float sq = 0.0f, sk2 = 0.0f;
    for (int i = threadIdx.x; i < NN; i += 256) {
        float a = q[i]; sq += a*a;
        float e = k[i]; sk2 += e*e;
    }
    __shared__ float r1[256], r2[256];
    r1[threadIdx.x] = sq; r2[threadIdx.x] = sk2;
    __syncthreads();
    for (int s = 128; s > 0; s >>= 1) {
        if (threadIdx.x < s) { r1[threadIdx.x] += r1[threadIdx.x+s]; r2[threadIdx.x] += r2[threadIdx.x+s]; }
        __syncthreads();
    }
    if (threadIdx.x == 0) { g_nq[bc] = sqrtf(r1[0]); g_nk[bc] = sqrtf(r2[0]); }
}

// K10: raw 8x8 Gram per (b,head) via permuted gathers (idx from item low bits)
__global__ __launch_bounds__(256) void k_attn() {
    int bh = blockIdx.x; int b = bh >> 3, h = bh & 7;
    const float* qp = g_dw + (b*192 + h*8)*NN;
    const float* kp = g_dw + (b*192 + 64 + h*8)*NN;
    const ull* vp = g_keys1 + (b*64 + h*8)*NN;
    float acc[64];
#pragma unroll
    for (int m = 0; m < 64; m++) acc[m] = 0.0f;
    int i0 = blockIdx.y * 4096;
    for (int i = i0 + threadIdx.x; i < i0 + 4096; i += 256) {
        unsigned id[8]; float qv[8], kv[8];
#pragma unroll
        for (int c = 0; c < 8; c++) id[c] = (unsigned)(vp[c*NN + i] & 0xFFFFu);
#pragma unroll
        for (int c = 0; c < 8; c++) { qv[c] = qp[c*NN + id[c]]; kv[c] = kp[c*NN + id[c]]; }
#pragma unroll
        for (int c = 0; c < 8; c++)
#pragma unroll
            for (int d = 0; d < 8; d++) acc[c*8+d] += qv[c]*kv[d];
    }
#pragma unroll
    for (int m = 0; m < 64; m++) {
#pragma unroll
        for (int s = 16; s > 0; s >>= 1)
            acc[m] += __shfl_down_sync(0xffffffffu, acc[m], s);
    }
    if ((threadIdx.x & 31) == 0)
#pragma unroll
        for (int m = 0; m < 64; m++)
            atomicAdd(&g_attnraw[bh*64 + m], acc[m]);
}

// K11: normalize + temperature + softmax
__global__ __launch_bounds__(512) void k_softmax(const float* __restrict__ temp) {
    int t = threadIdx.x;
    int b = t >> 6, h = (t >> 3) & 7, c = t & 7;
    int bh = b*8 + h;
    float nq = fmaxf(g_nq[b*64 + h*8 + c], 1e-12f);
    float tp = temp[h];
    float a[8];
    float mx = -FLT_MAX;
#pragma unroll
    for (int d = 0; d < 8; d++) {
        float nk = fmaxf(g_nk[b*64 + h*8 + d], 1e-12f);
        a[d] = g_attnraw[bh*64 + c*8 + d] / (nq*nk) * tp;
        mx = fmaxf(mx, a[d]);
    }
    float s = 0.0f;
#pragma unroll
    for (int d = 0; d < 8; d++) { a[d] = expf(a[d] - mx); s += a[d]; }
    float inv = 1.0f / s;
#pragma unroll
    for (int d = 0; d < 8; d++) g_attn[bh*64 + c*8 + d] = a[d]*inv;
}

// K12: out = attn @ v_s, scattered back to unsorted positions
__global__ __launch_bounds__(256) void k_av() {
    int bh = blockIdx.y; int b = bh >> 3, h = bh & 7;
    __shared__ float a[64];
    if (threadIdx.x < 64) a[threadIdx.x] = g_attn[bh*64 + threadIdx.x];
    __syncthreads();
    int n = blockIdx.x*256 + threadIdx.x;
    int base = (b*64 + h*8)*NN;
    float v[8]; unsigned id[8];
#pragma unroll
    for (int d = 0; d < 8; d++) {
        ull item = g_keys1[base + d*NN + n];
        v[d] = fdec((unsigned)(item >> 16));
        id[d] = (unsigned)(item & 0xFFFFu);
    }
#pragma unroll
    for (int c = 0; c < 8; c++) {
        float s = 0.0f;
#pragma unroll
        for (int d = 0; d < 8; d++) s += a[c*8+d]*v[d];
        g_out[base + c*NN + id[c]] = s;
    }
}

// K13: per-channel sum/max over spatial
__global__ __launch_bounds__(256) void k_chstats() {
    int bc = blockIdx.x;
    const float* p = g_out + (size_t)bc*NN;
    float s = 0.0f, m = -FLT_MAX;
    for (int i = threadIdx.x; i < NN; i += 256) { float v = p[i]; s += v; m = fmaxf(m, v); }
    __shared__ float r1[256], r2[256];
    r1[threadIdx.x] = s; r2[threadIdx.x] = m;
    __syncthreads();
    for (int st = 128; st > 0; st >>= 1) {
        if (threadIdx.x < st) { r1[threadIdx.x] += r1[threadIdx.x+st]; r2[threadIdx.x] = fmaxf(r2[threadIdx.x], r2[threadIdx.x+st]); }
        __syncthreads();
    }
    if (threadIdx.x == 0) { g_chsum[bc] = r1[0]; g_chmax[bc] = r2[0]; }
}

// K14: channel attention
__global__ __launch_bounds__(64) void k_ca(const float* __restrict__ wfc1, const float* __restrict__ wfc2) {
    int b = blockIdx.x, c = threadIdx.x;
    __shared__ float mv[64], xv[64];
    mv[c] = g_chsum[b*64 + c] * (1.0f/65536.0f);
    xv[c] = g_chmax[b*64 + c];
    __syncthreads();
    float r1[4], r2[4];
#pragma unroll
    for (int j = 0; j < 4; j++) {
        float s1 = 0.0f, s2 = 0.0f;
        for (int cc = 0; cc < 64; cc++) {
            float w = wfc1[j*64 + cc];
            s1 += mv[cc]*w; s2 += xv[cc]*w;
        }
        r1[j] = s1 * sigm(s1);
        r2[j] = s2 * sigm(s2);
    }
    float t1 = 0.0f, t2 = 0.0f;
#pragma unroll
    for (int j = 0; j < 4; j++) { t1 += r1[j]*wfc2[c*4 + j]; t2 += r2[j]*wfc2[c*4 + j]; }
    g_ca[b*64 + c] = sigm(t1) + sigm(t2);
}

// K15: spatial stats
__global__ __launch_bounds__(256) void k_sp() {
    int b = blockIdx.y;
    int n = blockIdx.x*256 + threadIdx.x;
    __shared__ float cas[64];
    if (threadIdx.x < 64) cas[threadIdx.x] = g_ca[b*64 + threadIdx.x];
    __syncthreads();
    float s = 0.0f, mx = -FLT_MAX, mn = FLT_MAX;
    for (int c = 0; c < 64; c++) {
        float v = g_out[(b*64 + c)*NN + n] * cas[c];
        s += v; mx = fmaxf(mx, v); mn = fminf(mn, v);
    }
    g_sp[(b*4 + 0)*NN + n] = s * (1.0f/64.0f);
    g_sp[(b*4 + 1)*NN + n] = mx;
    g_sp[(b*4 + 2)*NN + n] = mn;
    g_sp[(b*4 + 3)*NN + n] = s;
}

// K16: 7x7 conv (4->1) + silu + 1x1 + sigmoid
__global__ __launch_bounds__(256) void k_sa(const float* __restrict__ wsp1, const float* __restrict__ bsp1,
                                            const float* __restrict__ wsp2, const float* __restrict__ bsp2) {
    __shared__ float tile[4][22][22];
    __shared__ float ws[196];
    int b = blockIdx.z;
    int y0 = blockIdx.y*16, x0 = blockIdx.x*16;
    int tx = threadIdx.x & 15, ty = threadIdx.x >> 4;
    int tid = threadIdx.x;
    if (tid < 196) ws[tid] = wsp1[tid];
    for (int m = tid; m < 4*484; m += 256) {
        int ic = m / 484, rr = m % 484;
        int iy = rr / 22, ix = rr % 22;
        int gy = y0 + iy - 3, gx = x0 + ix - 3;
        tile[ic][iy][ix] = (gy >= 0 && gy < 256 && gx >= 0 && gx < 256)
                           ? g_sp[(b*4 + ic)*NN + gy*256 + gx] : 0.0f;
    }
    __syncthreads();
    float acc = 0.0f;
#pragma unroll
    for (int ic = 0; ic < 4; ic++)
#pragma unroll
        for (int ky = 0; ky < 7; ky++)
#pragma unroll
            for (int kx = 0; kx < 7; kx++)
                acc += ws[ic*49 + ky*7 + kx] * tile[ic][ty+ky][tx+kx];
    float s = acc + bsp1[0];
    float sl = s * sigm(s);
    float t2 = wsp2[0]*sl + bsp2[0];
    g_sa[b*NN + (y0+ty)*256 + x0+tx] = sigm(t2);
}

// K17: projection GEMM + ca*sa scaling + inverse permutations (c<32)
__global__ __launch_bounds__(256) void k_proj(const float* __restrict__ wproj, float* __restrict__ out) {
    __shared__ float xs[64][128];
    __shared__ float wp[64][64];
    __shared__ float sas[128];
    __shared__ float cas[64];
    int b = blockIdx.y;
    int p0 = blockIdx.x * 128, t = threadIdx.x;
    if (t < 64) cas[t] = g_ca[b*64 + t];
    if (t < 128) sas[t] = g_sa[b*NN + p0 + t];
    __syncthreads();
    for (int m = t; m < 64*128; m += 256) {
        int c = m >> 7, px = m & 127;
        xs[c][px] = g_out[(b*64 + c)*NN + p0 + px] * cas[c];
    }
    for (int m = t; m < 4096; m += 256) {
        int o = m >> 6, c = m & 63;
        wp[o][c] = wproj[o*64 + c];
    }
    __syncthreads();
    int ob = (t >> 5) * 8, pb = (t & 31) * 4;
    float acc[8][4];
#pragma unroll
    for (int u = 0; u < 8; u++)
#pragma unroll
        for (int v = 0; v < 4; v++) acc[u][v] = 0.0f;
#pragma unroll 8
    for (int c = 0; c < 64; c++) {
        float4 xv = *(const float4*)&xs[c][pb];
        float wv[8];
#pragma unroll
        for (int u = 0; u < 8; u++) wv[u] = wp[ob + u][c];
#pragma unroll
        for (int u = 0; u < 8; u++) {
            acc[u][0] += wv[u]*xv.x; acc[u][1] += wv[u]*xv.y;
            acc[u][2] += wv[u]*xv.z; acc[u][3] += wv[u]*xv.w;
        }
    }
#pragma unroll
    for (int u = 0; u < 8; u++) {
        int o = ob + u;
        if (o >= 32) {
#pragma unroll
            for (int v = 0; v < 4; v++)
                out[(b*64 + o)*NN + p0 + pb + v] = acc[u][v] * sas[pb + v];
        } else {
            int ibase = (b*32 + o) * NN;
#pragma unroll
            for (int v = 0; v < 4; v++) {
                int n = p0 + pb + v;
                int q = n >> 8, p = n & 255;
                int j = (int)g_idxw[ibase + q*256 + p];
                int r = (int)g_idxh[ibase + q*256 + j];
                out[(b*64 + o)*NN + r*256 + j] = acc[u][v] * sas[pb + v];
            }
        }
    }
}

extern "C" void kernel_launch(void* const* d_in, const int* in_sizes, int n_in,
                              void* d_out, int out_size) {
    const float* x     = (const float*)d_in[0];
    const float* temp  = (const float*)d_in[1];
    const float* wqkv  = (const float*)d_in[2];
    const float* wdw   = (const float*)d_in[3];
    const float* wfc1  = (const float*)d_in[4];
    const float* wfc2  = (const float*)d_in[5];
    const float* wsp1  = (const float*)d_in[6];
    const float* bsp1  = (const float*)d_in[7];
    const float* wsp2  = (const float*)d_in[8];
    const float* bsp2  = (const float*)d_in[9];
    const float* wproj = (const float*)d_in[10];
    float* out = (float*)d_out;

    void *pS0, *pS1, *pattn;
    cudaGetSymbolAddress(&pS0, g_qkv);
    cudaGetSymbolAddress(&pS1, g_keys1);
    cudaGetSymbolAddress(&pattn, g_attnraw);
    ull* S0 = (ull*)pS0;
    ull* S1 = (ull*)pS1;

    k_colsort<<<8192, 256>>>(x);
    k_rowsort<<<65536, 128>>>();
    k_copyhalf<<<65536, 256>>>(x);
    k_qkv<<<dim3(NN/128, 3, BB), 256>>>(wqkv);
    k_dwconv<<<dim3(BB*C3, NN/256), 256>>>(wdw);

    // custom segmented radix sort: 3 passes, 8-bit digits, bits [24,48)
    k_mkkeys<<<8192, 256>>>(S0);
    k_scan<<<512, 256>>>();
    k_scatter<<<8192, 256>>>(S0, S1, 24);
    k_count<<<8192, 256>>>(S1, 32);
    k_scan<<<512, 256>>>();
    k_scatter<<<8192, 256>>>(S1, S0, 32);
    k_count<<<8192, 256>>>(S0, 40);
    k_scan<<<512, 256>>>();
    k_scatter<<<8192, 256>>>(S0, S1, 40);   // final items in g_keys1

    k_norms<<<BB*CC, 256>>>();
    cudaMemsetAsync(pattn, 0, sizeof(float)*BB*HEADS*64);
    k_attn<<<dim3(BB*HEADS, 16), 256>>>();
    k_softmax<<<1, 512>>>(temp);
    k_av<<<dim3(NN/256, BB*HEADS), 256>>>();
    k_chstats<<<BB*CC, 256>>>();
    k_ca<<<BB, 64>>>(wfc1, wfc2);
    k_sp<<<dim3(NN/256, BB), 256>>>();
    k_sa<<<dim3(16, 16, BB), 256>>>(wsp1, bsp1, wsp2, bsp2);
    k_proj<<<dim3(NN/128, BB), 256>>>(wproj, out);
}